// round 15
// baseline (speedup 1.0000x reference)
#include <cuda_runtime.h>
#include <math.h>

#define B_   2
#define T_   16
#define H_   32
#define W_   32
#define C_   192
#define L_   16384          // T_*H_*W_
#define DI_  384
#define DS_  16
#define XW_  44             // DT_RANK(12) + 2*D_STATE(32)
#define EPS_ 1e-5f

// ---------------- scratch (static device memory; no allocation) ----------------
__device__ float g_buf1 [B_*L_*C_];
__device__ float g_buf2 [B_*L_*C_];
__device__ float g_xnorm[B_*L_*C_];
__device__ float g_xz   [B_*L_*2*DI_];
__device__ float g_u    [B_*L_*DI_];
__device__ float g_xdb  [B_*L_*XW_];
__device__ float g_delta[B_*L_*DI_];
__device__ float g_y    [B_*L_*DI_];
__device__ float g_wrp1 [27*C_*C_];
__device__ float g_wrp2 [27*C_*C_];
__device__ float g_psum [B_*128*C_];
__device__ float g_psq  [B_*128*C_];
__device__ float g_mean [B_*C_];
__device__ float g_rstd [B_*C_];
__device__ float g_Aneg [DI_*DS_];

// ---------------- helpers ----------------
__device__ __forceinline__ float softplusf(float x) {
    return fmaxf(x, 0.f) + log1pf(expf(-fabsf(x)));
}

// Repack conv weight w[o][i][dt][dh][dw] -> wr[(dt*3+dh)][i][dw][o] (o contiguous)
__global__ void repack_w(const float* __restrict__ w, float* __restrict__ wr) {
    int id = blockIdx.x * blockDim.x + threadIdx.x;
    if (id >= 27 * C_ * C_) return;
    int o  = id % C_;  int r = id / C_;
    int dw = r % 3;    r /= 3;
    int ci = r % C_;   int dtdh = r / C_;
    wr[id] = w[(size_t)o * (C_ * 27) + (size_t)ci * 27 + dtdh * 3 + dw];
}

// 3x3x3 conv, channels-last (B,T,H,W,C). Block = (b,t,h) row: 192 out ch x 32 W.
__global__ __launch_bounds__(256, 2) void conv3d_k(
    const float* __restrict__ in, const float* __restrict__ wr,
    const float* __restrict__ bias, float* __restrict__ out)
{
    int h = blockIdx.x, t = blockIdx.y, b = blockIdx.z;
    int tid = threadIdx.x;
    int tm = tid >> 3;      // 0..31 -> out-channel group of 6
    int tn = tid & 7;       // 0..7  -> W group of 4
    __shared__ float Ws[8][3][C_];   // [kc][dw][o]
    __shared__ float Is[8][36];      // [kc][wp], wp = w+1 in [0,33]

    float acc[6][4];
#pragma unroll
    for (int i = 0; i < 6; ++i) {
        float bv = bias[tm * 6 + i];
#pragma unroll
        for (int j = 0; j < 4; ++j) acc[i][j] = bv;
    }

    for (int dtdh = 0; dtdh < 9; ++dtdh) {
        int dt = dtdh / 3, dh = dtdh - dt * 3;
        int tt = t + dt - 1, hh = h + dh - 1;
        if (tt < 0 || tt >= T_ || hh < 0 || hh >= H_) continue;   // block-uniform
        const float* inrow = in + ((((size_t)b * T_ + tt) * H_ + hh) * W_) * C_;
        const float* wbase = wr + (size_t)dtdh * C_ * 3 * C_;
        for (int ci0 = 0; ci0 < C_; ci0 += 8) {
            __syncthreads();
            for (int e = tid; e < 34 * 8; e += 256) {
                int wp = e >> 3, kc = e & 7;
                int w = wp - 1;
                Is[kc][wp] = (w >= 0 && w < W_) ? inrow[w * C_ + ci0 + kc] : 0.f;
            }
            for (int e = tid; e < 8 * 3 * C_; e += 256) {
                int o = e % C_; int r = e / C_;
                int dw = r % 3, kc = r / 3;
                Ws[kc][dw][o] = wbase[((ci0 + kc) * 3 + dw) * C_ + o];
            }
            __syncthreads();
#pragma unroll
            for (int kc = 0; kc < 8; ++kc) {
                float bv[6];
#pragma unroll
                for (int j = 0; j < 6; ++j) bv[j] = Is[kc][tn * 4 + j];
#pragma unroll
                for (int dw = 0; dw < 3; ++dw) {
                    float av[6];
#pragma unroll
                    for (int i = 0; i < 6; ++i) av[i] = Ws[kc][dw][tm * 6 + i];
#pragma unroll
                    for (int i = 0; i < 6; ++i)
#pragma unroll
                        for (int j = 0; j < 4; ++j)
                            acc[i][j] = fmaf(av[i], bv[j + dw], acc[i][j]);
                }
            }
        }
    }
    float* orow = out + ((((size_t)b * T_ + t) * H_ + h) * W_) * C_;
#pragma unroll
    for (int j = 0; j < 4; ++j)
#pragma unroll
        for (int i = 0; i < 6; ++i)
            orow[(tn * 4 + j) * C_ + tm * 6 + i] = acc[i][j];
}

// Instance-norm partial sums: grid (128, B), block 192 (thread = channel)
__global__ void inorm_part(const float* __restrict__ x,
                           float* __restrict__ ps, float* __restrict__ pq) {
    int c = threadIdx.x;
    int blk = blockIdx.x, b = blockIdx.y;
    const float* base = x + ((size_t)b * L_ + (size_t)blk * 128) * C_ + c;
    float s = 0.f, q = 0.f;
    for (int p = 0; p < 128; ++p) {
        float v = base[(size_t)p * C_];
        s += v; q += v * v;
    }
    ps[((size_t)b * 128 + blk) * C_ + c] = s;
    pq[((size_t)b * 128 + blk) * C_ + c] = q;
}

__global__ void inorm_fin(const float* __restrict__ ps, const float* __restrict__ pq,
                          float* __restrict__ mean, float* __restrict__ rstd) {
    int c = threadIdx.x, b = blockIdx.x;
    float s = 0.f, q = 0.f;
    for (int k = 0; k < 128; ++k) {
        s += ps[((size_t)b * 128 + k) * C_ + c];
        q += pq[((size_t)b * 128 + k) * C_ + c];
    }
    float m = s * (1.f / L_);
    float v = q * (1.f / L_) - m * m;
    mean[b * C_ + c] = m;
    rstd[b * C_ + c] = rsqrtf(v + EPS_);
}

__global__ void ew_leaky(float* __restrict__ buf, const float* __restrict__ mean,
                         const float* __restrict__ rstd) {
    size_t idx = (size_t)blockIdx.x * blockDim.x + threadIdx.x;
    if (idx >= (size_t)B_ * L_ * C_) return;
    int c = (int)(idx % C_);
    int b = (int)(idx / ((size_t)L_ * C_));
    float v = (buf[idx] - mean[b * C_ + c]) * rstd[b * C_ + c];
    buf[idx] = v > 0.f ? v : 0.01f * v;
}

__global__ void ew_res(float* __restrict__ buf, const float* __restrict__ mean,
                       const float* __restrict__ rstd, const float* __restrict__ x) {
    size_t idx = (size_t)blockIdx.x * blockDim.x + threadIdx.x;
    if (idx >= (size_t)B_ * L_ * C_) return;
    int c = (int)(idx % C_);
    int b = (int)(idx / ((size_t)L_ * C_));
    buf[idx] = (buf[idx] - mean[b * C_ + c]) * rstd[b * C_ + c] + x[idx];
}

// LayerNorm over the reshaped features: feature d of token l = xl[b*L*C + d*L + l]
__global__ void weird_ln(const float* __restrict__ xl, const float* __restrict__ g,
                         const float* __restrict__ bb, float* __restrict__ xn) {
    int idx = blockIdx.x * blockDim.x + threadIdx.x;
    if (idx >= B_ * L_) return;
    int b = idx / L_, l = idx % L_;
    const float* base = xl + (size_t)b * L_ * C_ + l;
    float s = 0.f, q = 0.f;
#pragma unroll 4
    for (int d = 0; d < C_; ++d) {
        float v = base[(size_t)d * L_];
        s += v; q += v * v;
    }
    float m = s * (1.f / C_);
    float var = q * (1.f / C_) - m * m;
    float rs = rsqrtf(var + EPS_);
    float* o = xn + (size_t)idx * C_;
#pragma unroll 4
    for (int d = 0; d < C_; ++d) {
        float v = base[(size_t)d * L_];
        o[d] = (v - m) * rs * g[d] + bb[d];
    }
}

// C[M,N] = A[M,K] * B[N,K]^T ; act=1 -> softplus(C + bias[col])
__global__ __launch_bounds__(256, 2) void sgemm_nt(
    const float* __restrict__ A, const float* __restrict__ Bm, float* __restrict__ C,
    int M, int N, int K, int lda, int ldb, int ldc,
    const float* __restrict__ bias, int act)
{
    __shared__ __align__(16) float As[16][132];
    __shared__ __align__(16) float Bs[16][68];
    int m0 = blockIdx.y * 128, n0 = blockIdx.x * 64;
    int tid = threadIdx.x;
    int tm = tid >> 4, tn = tid & 15;
    float acc[8][4];
#pragma unroll
    for (int i = 0; i < 8; ++i)
#pragma unroll
        for (int j = 0; j < 4; ++j) acc[i][j] = 0.f;

    for (int k0 = 0; k0 < K; k0 += 16) {
#pragma unroll
        for (int it = 0; it < 2; ++it) {
            int e = tid + it * 256;
            int row = e >> 2, kq = (e & 3) << 2;
            int gr = m0 + row, gk = k0 + kq;
            float4 v = make_float4(0.f, 0.f, 0.f, 0.f);
            if (gr < M && gk < K) v = *(const float4*)(A + (size_t)gr * lda + gk);
            As[kq + 0][row] = v.x; As[kq + 1][row] = v.y;
            As[kq + 2][row] = v.z; As[kq + 3][row] = v.w;
        }
        {
            int row = tid >> 2, kq = (tid & 3) << 2;
            int gr = n0 + row, gk = k0 + kq;
            float4 v = make_float4(0.f, 0.f, 0.f, 0.f);
            if (gr < N && gk < K) v = *(const float4*)(Bm + (size_t)gr * ldb + gk);
            Bs[kq + 0][row] = v.x; Bs[kq + 1][row] = v.y;
            Bs[kq + 2][row] = v.z; Bs[kq + 3][row] = v.w;
        }
        __syncthreads();
#pragma unroll
        for (int kc = 0; kc < 16; ++kc) {
            float a[8], bv[4];
            *(float4*)&a[0] = *(const float4*)&As[kc][tm * 8];
            *(float4*)&a[4] = *(const float4*)&As[kc][tm * 8 + 4];
            *(float4*)&bv[0] = *(const float4*)&Bs[kc][tn * 4];
#pragma unroll
            for (int i = 0; i < 8; ++i)
#pragma unroll
                for (int j = 0; j < 4; ++j)
                    acc[i][j] = fmaf(a[i], bv[j], acc[i][j]);
        }
        __syncthreads();
    }
#pragma unroll
    for (int i = 0; i < 8; ++i) {
        int gr = m0 + tm * 8 + i;
        if (gr >= M) continue;
#pragma unroll
        for (int j = 0; j < 4; ++j) {
            int gc = n0 + tn * 4 + j;
            if (gc >= N) continue;
            float v = acc[i][j];
            if (act) v = softplusf(v + bias[gc]);
            C[(size_t)gr * ldc + gc] = v;
        }
    }
}

// depthwise causal conv1d (k=4, left pad 3) + SiLU; input = first DI cols of xz
__global__ void conv1d_silu(const float* __restrict__ xz, const float* __restrict__ w,
                            const float* __restrict__ bias, float* __restrict__ u) {
    size_t idx = (size_t)blockIdx.x * blockDim.x + threadIdx.x;
    if (idx >= (size_t)B_ * L_ * DI_) return;
    int c = (int)(idx % DI_);
    size_t m = idx / DI_;
    int l = (int)(m % L_);
    size_t rowb = m - (size_t)l;     // b*L_
    float acc = bias[c];
#pragma unroll
    for (int k = 0; k < 4; ++k) {
        int ll = l - 3 + k;
        if (ll >= 0)
            acc = fmaf(w[c * 4 + k], xz[(rowb + ll) * (size_t)(2 * DI_) + c], acc);
    }
    u[idx] = acc / (1.f + __expf(-acc));
}

__global__ void prep_A(const float* __restrict__ alog, float* __restrict__ an) {
    int i = blockIdx.x * blockDim.x + threadIdx.x;
    if (i < DI_ * DS_) an[i] = -expf(alog[i]);
}

// Selective scan. Block = (b, 8 channels); thread = (ci, state s). Fused epilogue.
__global__ __launch_bounds__(128) void scan_k(
    const float* __restrict__ delta, const float* __restrict__ u,
    const float* __restrict__ xz, const float* __restrict__ xdb,
    const float* __restrict__ An, const float* __restrict__ Dp,
    float* __restrict__ y)
{
    __shared__ float sD[64][8], sU[64][8], sZ[64][8];
    __shared__ float sB[64][16], sC[64][16];
    int b = blockIdx.y;
    int cg = blockIdx.x;
    int tid = threadIdx.x;
    int ci = tid >> 4, s = tid & 15;
    int c = cg * 8 + ci;
    float Ac = An[c * DS_ + s];
    float Dc = Dp[c];
    float h = 0.f;
    size_t tokb = (size_t)b * L_;
    int c8 = cg * 8;

    for (int l0 = 0; l0 < L_; l0 += 64) {
        __syncthreads();
        for (int e = tid; e < 512; e += 128) {
            int j = e >> 3, cc = e & 7;
            size_t r = tokb + l0 + j;
            sD[j][cc] = delta[r * DI_ + c8 + cc];
            sU[j][cc] = u[r * DI_ + c8 + cc];
            sZ[j][cc] = xz[r * (size_t)(2 * DI_) + DI_ + c8 + cc];
        }
        for (int e = tid; e < 1024; e += 128) {
            int j = e >> 4, ss = e & 15;
            size_t r = tokb + l0 + j;
            sB[j][ss] = xdb[r * XW_ + 12 + ss];
            sC[j][ss] = xdb[r * XW_ + 28 + ss];
        }
        __syncthreads();
#pragma unroll 8
        for (int j = 0; j < 64; ++j) {
            float dlt = sD[j][ci];
            float ut  = sU[j][ci];
            float ex  = __expf(dlt * Ac);          // off the h critical path
            float f   = dlt * ut * sB[j][s];
            h = fmaf(ex, h, f);                    // only loop-carried dep
            float py = h * sC[j][s];
            py += __shfl_xor_sync(0xffffffffu, py, 8, 16);
            py += __shfl_xor_sync(0xffffffffu, py, 4, 16);
            py += __shfl_xor_sync(0xffffffffu, py, 2, 16);
            py += __shfl_xor_sync(0xffffffffu, py, 1, 16);
            if (s == 0) {
                float z = sZ[j][ci];
                float sil = z / (1.f + __expf(-z));
                y[(tokb + l0 + j) * DI_ + c] = (py + ut * Dc) * sil;
            }
        }
    }
}

// ---------------- launcher ----------------
extern "C" void kernel_launch(void* const* d_in, const int* in_sizes, int n_in,
                              void* d_out, int out_size)
{
    const float* x        = (const float*)d_in[0];
    const float* conv1w   = (const float*)d_in[1];
    const float* conv1b   = (const float*)d_in[2];
    const float* conv2w   = (const float*)d_in[3];
    const float* conv2b   = (const float*)d_in[4];
    const float* ln_g     = (const float*)d_in[5];
    const float* ln_b     = (const float*)d_in[6];
    const float* inprojw  = (const float*)d_in[7];
    const float* c1dw     = (const float*)d_in[8];
    const float* c1db     = (const float*)d_in[9];
    const float* xprojw   = (const float*)d_in[10];
    const float* dtprojw  = (const float*)d_in[11];
    const float* dtprojb  = (const float*)d_in[12];
    const float* A_log    = (const float*)d_in[13];
    const float* Dp       = (const float*)d_in[14];
    const float* outprojw = (const float*)d_in[15];
    float* out = (float*)d_out;

    float *buf1, *buf2, *xnorm, *xz, *u, *xdb, *delta, *y;
    float *wrp1, *wrp2, *psum, *psq, *mean, *rstd, *Aneg;
    void* p;
    cudaGetSymbolAddress(&p, g_buf1);  buf1  = (float*)p;
    cudaGetSymbolAddress(&p, g_buf2);  buf2  = (float*)p;
    cudaGetSymbolAddress(&p, g_xnorm); xnorm = (float*)p;
    cudaGetSymbolAddress(&p, g_xz);    xz    = (float*)p;
    cudaGetSymbolAddress(&p, g_u);     u     = (float*)p;
    cudaGetSymbolAddress(&p, g_xdb);   xdb   = (float*)p;
    cudaGetSymbolAddress(&p, g_delta); delta = (float*)p;
    cudaGetSymbolAddress(&p, g_y);     y     = (float*)p;
    cudaGetSymbolAddress(&p, g_wrp1);  wrp1  = (float*)p;
    cudaGetSymbolAddress(&p, g_wrp2);  wrp2  = (float*)p;
    cudaGetSymbolAddress(&p, g_psum);  psum  = (float*)p;
    cudaGetSymbolAddress(&p, g_psq);   psq   = (float*)p;
    cudaGetSymbolAddress(&p, g_mean);  mean  = (float*)p;
    cudaGetSymbolAddress(&p, g_rstd);  rstd  = (float*)p;
    cudaGetSymbolAddress(&p, g_Aneg);  Aneg  = (float*)p;

    const int M = B_ * L_;               // 32768 tokens
    dim3 cgrid(H_, T_, B_);

    // conv weight repack (both)
    repack_w<<<(27 * C_ * C_ + 255) / 256, 256>>>(conv1w, wrp1);
    repack_w<<<(27 * C_ * C_ + 255) / 256, 256>>>(conv2w, wrp2);

    // conv1 -> inorm -> leaky
    conv3d_k<<<cgrid, 256>>>(x, wrp1, conv1b, buf1);
    inorm_part<<<dim3(128, B_), 192>>>(buf1, psum, psq);
    inorm_fin<<<B_, 192>>>(psum, psq, mean, rstd);
    ew_leaky<<<(B_ * L_ * C_ + 255) / 256, 256>>>(buf1, mean, rstd);

    // conv2 -> inorm -> +residual(x)
    conv3d_k<<<cgrid, 256>>>(buf1, wrp2, conv2b, buf2);
    inorm_part<<<dim3(128, B_), 192>>>(buf2, psum, psq);
    inorm_fin<<<B_, 192>>>(psum, psq, mean, rstd);
    ew_res<<<(B_ * L_ * C_ + 255) / 256, 256>>>(buf2, mean, rstd, x);

    // reshaped LayerNorm
    weird_ln<<<(B_ * L_ + 255) / 256, 256>>>(buf2, ln_g, ln_b, xnorm);

    // xz = xnorm @ in_proj^T   (M x 768, K=192)
    sgemm_nt<<<dim3(768 / 64, M / 128), 256>>>(xnorm, inprojw, xz,
                                               M, 2 * DI_, C_, C_, C_, 2 * DI_, nullptr, 0);
    // depthwise conv1d + silu -> u
    conv1d_silu<<<(B_ * L_ * DI_ + 255) / 256, 256>>>(xz, c1dw, c1db, u);

    // xdb = u @ x_proj^T   (M x 44, K=384)
    sgemm_nt<<<dim3(1, M / 128), 256>>>(u, xprojw, xdb,
                                        M, XW_, DI_, DI_, DI_, XW_, nullptr, 0);
    // delta = softplus(dt @ dt_proj^T + b)   (M x 384, K=12, A stride 44)
    sgemm_nt<<<dim3(DI_ / 64, M / 128), 256>>>(xdb, dtprojw, delta,
                                               M, DI_, 12, XW_, 12, DI_, dtprojb, 1);

    // A = -exp(A_log)
    prep_A<<<(DI_ * DS_ + 255) / 256, 256>>>(A_log, Aneg);

    // selective scan (+u*Dp, *silu(z) fused)
    scan_k<<<dim3(DI_ / 8, B_), 128>>>(delta, u, xz, xdb, Aneg, Dp, y);

    // out = y @ out_proj^T   (M x 192, K=384) -> d_out
    sgemm_nt<<<dim3(C_ / 64, M / 128), 256>>>(y, outprojw, out,
                                              M, C_, DI_, DI_, DI_, C_, nullptr, 0);
}

// round 16
// speedup vs baseline: 1.0013x; 1.0013x over previous
#include <cuda_runtime.h>
#include <math.h>

#define B_   2
#define T_   16
#define H_   32
#define W_   32
#define C_   192
#define L_   16384          // T_*H_*W_
#define DI_  384
#define DS_  16
#define XW_  44             // DT_RANK(12) + 2*D_STATE(32)
#define EPS_ 1e-5f

// ---------------- scratch (static device memory; no allocation) ----------------
__device__ float g_buf1 [B_*L_*C_];
__device__ float g_buf2 [B_*L_*C_];
__device__ float g_xnorm[B_*L_*C_];
__device__ float g_xz   [B_*L_*2*DI_];
__device__ float g_u    [B_*L_*DI_];
__device__ float g_xdb  [B_*L_*XW_];
__device__ float g_delta[B_*L_*DI_];
__device__ float g_y    [B_*L_*DI_];
__device__ float g_wrp1 [27*C_*C_];
__device__ float g_wrp2 [27*C_*C_];
__device__ float g_psum [B_*128*C_];
__device__ float g_psq  [B_*128*C_];
__device__ float g_mean [B_*C_];
__device__ float g_rstd [B_*C_];
__device__ float g_Aneg [DI_*DS_];

// ---------------- helpers ----------------
__device__ __forceinline__ float softplusf(float x) {
    return fmaxf(x, 0.f) + log1pf(expf(-fabsf(x)));
}

// Repack conv weight w[o][i][dt][dh][dw] -> wr[(dt*3+dh)][i][dw][o] (o contiguous)
__global__ void repack_w(const float* __restrict__ w, float* __restrict__ wr) {
    int id = blockIdx.x * blockDim.x + threadIdx.x;
    if (id >= 27 * C_ * C_) return;
    int o  = id % C_;  int r = id / C_;
    int dw = r % 3;    r /= 3;
    int ci = r % C_;   int dtdh = r / C_;
    wr[id] = w[(size_t)o * (C_ * 27) + (size_t)ci * 27 + dtdh * 3 + dw];
}

// 3x3x3 conv, channels-last (B,T,H,W,C). Block = (b,t,h) row: 192 out ch x 32 W.
__global__ __launch_bounds__(256, 2) void conv3d_k(
    const float* __restrict__ in, const float* __restrict__ wr,
    const float* __restrict__ bias, float* __restrict__ out)
{
    int h = blockIdx.x, t = blockIdx.y, b = blockIdx.z;
    int tid = threadIdx.x;
    int tm = tid >> 3;      // 0..31 -> out-channel group of 6
    int tn = tid & 7;       // 0..7  -> W group of 4
    __shared__ float Ws[8][3][C_];   // [kc][dw][o]
    __shared__ float Is[8][36];      // [kc][wp], wp = w+1 in [0,33]

    float acc[6][4];
#pragma unroll
    for (int i = 0; i < 6; ++i) {
        float bv = bias[tm * 6 + i];
#pragma unroll
        for (int j = 0; j < 4; ++j) acc[i][j] = bv;
    }

    for (int dtdh = 0; dtdh < 9; ++dtdh) {
        int dt = dtdh / 3, dh = dtdh - dt * 3;
        int tt = t + dt - 1, hh = h + dh - 1;
        if (tt < 0 || tt >= T_ || hh < 0 || hh >= H_) continue;   // block-uniform
        const float* inrow = in + ((((size_t)b * T_ + tt) * H_ + hh) * W_) * C_;
        const float* wbase = wr + (size_t)dtdh * C_ * 3 * C_;
        for (int ci0 = 0; ci0 < C_; ci0 += 8) {
            __syncthreads();
            for (int e = tid; e < 34 * 8; e += 256) {
                int wp = e >> 3, kc = e & 7;
                int w = wp - 1;
                Is[kc][wp] = (w >= 0 && w < W_) ? inrow[w * C_ + ci0 + kc] : 0.f;
            }
            for (int e = tid; e < 8 * 3 * C_; e += 256) {
                int o = e % C_; int r = e / C_;
                int dw = r % 3, kc = r / 3;
                Ws[kc][dw][o] = wbase[((ci0 + kc) * 3 + dw) * C_ + o];
            }
            __syncthreads();
#pragma unroll
            for (int kc = 0; kc < 8; ++kc) {
                float bv[6];
#pragma unroll
                for (int j = 0; j < 6; ++j) bv[j] = Is[kc][tn * 4 + j];
#pragma unroll
                for (int dw = 0; dw < 3; ++dw) {
                    float av[6];
#pragma unroll
                    for (int i = 0; i < 6; ++i) av[i] = Ws[kc][dw][tm * 6 + i];
#pragma unroll
                    for (int i = 0; i < 6; ++i)
#pragma unroll
                        for (int j = 0; j < 4; ++j)
                            acc[i][j] = fmaf(av[i], bv[j + dw], acc[i][j]);
                }
            }
        }
    }
    float* orow = out + ((((size_t)b * T_ + t) * H_ + h) * W_) * C_;
#pragma unroll
    for (int j = 0; j < 4; ++j)
#pragma unroll
        for (int i = 0; i < 6; ++i)
            orow[(tn * 4 + j) * C_ + tm * 6 + i] = acc[i][j];
}

// Instance-norm partial sums: grid (128, B), block 192 (thread = channel)
__global__ void inorm_part(const float* __restrict__ x,
                           float* __restrict__ ps, float* __restrict__ pq) {
    int c = threadIdx.x;
    int blk = blockIdx.x, b = blockIdx.y;
    const float* base = x + ((size_t)b * L_ + (size_t)blk * 128) * C_ + c;
    float s = 0.f, q = 0.f;
    for (int p = 0; p < 128; ++p) {
        float v = base[(size_t)p * C_];
        s += v; q += v * v;
    }
    ps[((size_t)b * 128 + blk) * C_ + c] = s;
    pq[((size_t)b * 128 + blk) * C_ + c] = q;
}

__global__ void inorm_fin(const float* __restrict__ ps, const float* __restrict__ pq,
                          float* __restrict__ mean, float* __restrict__ rstd) {
    int c = threadIdx.x, b = blockIdx.x;
    float s = 0.f, q = 0.f;
    for (int k = 0; k < 128; ++k) {
        s += ps[((size_t)b * 128 + k) * C_ + c];
        q += pq[((size_t)b * 128 + k) * C_ + c];
    }
    float m = s * (1.f / L_);
    float v = q * (1.f / L_) - m * m;
    mean[b * C_ + c] = m;
    rstd[b * C_ + c] = rsqrtf(v + EPS_);
}

__global__ void ew_leaky(float* __restrict__ buf, const float* __restrict__ mean,
                         const float* __restrict__ rstd) {
    size_t idx = (size_t)blockIdx.x * blockDim.x + threadIdx.x;
    if (idx >= (size_t)B_ * L_ * C_) return;
    int c = (int)(idx % C_);
    int b = (int)(idx / ((size_t)L_ * C_));
    float v = (buf[idx] - mean[b * C_ + c]) * rstd[b * C_ + c];
    buf[idx] = v > 0.f ? v : 0.01f * v;
}

__global__ void ew_res(float* __restrict__ buf, const float* __restrict__ mean,
                       const float* __restrict__ rstd, const float* __restrict__ x) {
    size_t idx = (size_t)blockIdx.x * blockDim.x + threadIdx.x;
    if (idx >= (size_t)B_ * L_ * C_) return;
    int c = (int)(idx % C_);
    int b = (int)(idx / ((size_t)L_ * C_));
    buf[idx] = (buf[idx] - mean[b * C_ + c]) * rstd[b * C_ + c] + x[idx];
}

// LayerNorm over the reshaped features: feature d of token l = xl[b*L*C + d*L + l]
__global__ void weird_ln(const float* __restrict__ xl, const float* __restrict__ g,
                         const float* __restrict__ bb, float* __restrict__ xn) {
    int idx = blockIdx.x * blockDim.x + threadIdx.x;
    if (idx >= B_ * L_) return;
    int b = idx / L_, l = idx % L_;
    const float* base = xl + (size_t)b * L_ * C_ + l;
    float s = 0.f, q = 0.f;
#pragma unroll 4
    for (int d = 0; d < C_; ++d) {
        float v = base[(size_t)d * L_];
        s += v; q += v * v;
    }
    float m = s * (1.f / C_);
    float var = q * (1.f / C_) - m * m;
    float rs = rsqrtf(var + EPS_);
    float* o = xn + (size_t)idx * C_;
#pragma unroll 4
    for (int d = 0; d < C_; ++d) {
        float v = base[(size_t)d * L_];
        o[d] = (v - m) * rs * g[d] + bb[d];
    }
}

// C[M,N] = A[M,K] * B[N,K]^T ; act=1 -> softplus(C + bias[col])
__global__ __launch_bounds__(256, 2) void sgemm_nt(
    const float* __restrict__ A, const float* __restrict__ Bm, float* __restrict__ C,
    int M, int N, int K, int lda, int ldb, int ldc,
    const float* __restrict__ bias, int act)
{
    __shared__ __align__(16) float As[16][132];
    __shared__ __align__(16) float Bs[16][68];
    int m0 = blockIdx.y * 128, n0 = blockIdx.x * 64;
    int tid = threadIdx.x;
    int tm = tid >> 4, tn = tid & 15;
    float acc[8][4];
#pragma unroll
    for (int i = 0; i < 8; ++i)
#pragma unroll
        for (int j = 0; j < 4; ++j) acc[i][j] = 0.f;

    for (int k0 = 0; k0 < K; k0 += 16) {
#pragma unroll
        for (int it = 0; it < 2; ++it) {
            int e = tid + it * 256;
            int row = e >> 2, kq = (e & 3) << 2;
            int gr = m0 + row, gk = k0 + kq;
            float4 v = make_float4(0.f, 0.f, 0.f, 0.f);
            if (gr < M && gk < K) v = *(const float4*)(A + (size_t)gr * lda + gk);
            As[kq + 0][row] = v.x; As[kq + 1][row] = v.y;
            As[kq + 2][row] = v.z; As[kq + 3][row] = v.w;
        }
        {
            int row = tid >> 2, kq = (tid & 3) << 2;
            int gr = n0 + row, gk = k0 + kq;
            float4 v = make_float4(0.f, 0.f, 0.f, 0.f);
            if (gr < N && gk < K) v = *(const float4*)(Bm + (size_t)gr * ldb + gk);
            Bs[kq + 0][row] = v.x; Bs[kq + 1][row] = v.y;
            Bs[kq + 2][row] = v.z; Bs[kq + 3][row] = v.w;
        }
        __syncthreads();
#pragma unroll
        for (int kc = 0; kc < 16; ++kc) {
            float a[8], bv[4];
            *(float4*)&a[0] = *(const float4*)&As[kc][tm * 8];
            *(float4*)&a[4] = *(const float4*)&As[kc][tm * 8 + 4];
            *(float4*)&bv[0] = *(const float4*)&Bs[kc][tn * 4];
#pragma unroll
            for (int i = 0; i < 8; ++i)
#pragma unroll
                for (int j = 0; j < 4; ++j)
                    acc[i][j] = fmaf(a[i], bv[j], acc[i][j]);
        }
        __syncthreads();
    }
#pragma unroll
    for (int i = 0; i < 8; ++i) {
        int gr = m0 + tm * 8 + i;
        if (gr >= M) continue;
#pragma unroll
        for (int j = 0; j < 4; ++j) {
            int gc = n0 + tn * 4 + j;
            if (gc >= N) continue;
            float v = acc[i][j];
            if (act) v = softplusf(v + bias[gc]);
            C[(size_t)gr * ldc + gc] = v;
        }
    }
}

// depthwise causal conv1d (k=4, left pad 3) + SiLU; input = first DI cols of xz
__global__ void conv1d_silu(const float* __restrict__ xz, const float* __restrict__ w,
                            const float* __restrict__ bias, float* __restrict__ u) {
    size_t idx = (size_t)blockIdx.x * blockDim.x + threadIdx.x;
    if (idx >= (size_t)B_ * L_ * DI_) return;
    int c = (int)(idx % DI_);
    size_t m = idx / DI_;
    int l = (int)(m % L_);
    size_t rowb = m - (size_t)l;     // b*L_
    float acc = bias[c];
#pragma unroll
    for (int k = 0; k < 4; ++k) {
        int ll = l - 3 + k;
        if (ll >= 0)
            acc = fmaf(w[c * 4 + k], xz[(rowb + ll) * (size_t)(2 * DI_) + c], acc);
    }
    u[idx] = acc / (1.f + __expf(-acc));
}

__global__ void prep_A(const float* __restrict__ alog, float* __restrict__ an) {
    int i = blockIdx.x * blockDim.x + threadIdx.x;
    if (i < DI_ * DS_) an[i] = -expf(alog[i]);
}

// Selective scan. Block = (b, 8 channels); thread = (ci, state s). Fused epilogue.
__global__ __launch_bounds__(128) void scan_k(
    const float* __restrict__ delta, const float* __restrict__ u,
    const float* __restrict__ xz, const float* __restrict__ xdb,
    const float* __restrict__ An, const float* __restrict__ Dp,
    float* __restrict__ y)
{
    __shared__ float sD[64][8], sU[64][8], sZ[64][8];
    __shared__ float sB[64][16], sC[64][16];
    int b = blockIdx.y;
    int cg = blockIdx.x;
    int tid = threadIdx.x;
    int ci = tid >> 4, s = tid & 15;
    int c = cg * 8 + ci;
    float Ac = An[c * DS_ + s];
    float Dc = Dp[c];
    float h = 0.f;
    size_t tokb = (size_t)b * L_;
    int c8 = cg * 8;

    for (int l0 = 0; l0 < L_; l0 += 64) {
        __syncthreads();
        for (int e = tid; e < 512; e += 128) {
            int j = e >> 3, cc = e & 7;
            size_t r = tokb + l0 + j;
            sD[j][cc] = delta[r * DI_ + c8 + cc];
            sU[j][cc] = u[r * DI_ + c8 + cc];
            sZ[j][cc] = xz[r * (size_t)(2 * DI_) + DI_ + c8 + cc];
        }
        for (int e = tid; e < 1024; e += 128) {
            int j = e >> 4, ss = e & 15;
            size_t r = tokb + l0 + j;
            sB[j][ss] = xdb[r * XW_ + 12 + ss];
            sC[j][ss] = xdb[r * XW_ + 28 + ss];
        }
        __syncthreads();
#pragma unroll 8
        for (int j = 0; j < 64; ++j) {
            float dlt = sD[j][ci];
            float ut  = sU[j][ci];
            float ex  = __expf(dlt * Ac);          // off the h critical path
            float f   = dlt * ut * sB[j][s];
            h = fmaf(ex, h, f);                    // only loop-carried dep
            float py = h * sC[j][s];
            py += __shfl_xor_sync(0xffffffffu, py, 8, 16);
            py += __shfl_xor_sync(0xffffffffu, py, 4, 16);
            py += __shfl_xor_sync(0xffffffffu, py, 2, 16);
            py += __shfl_xor_sync(0xffffffffu, py, 1, 16);
            if (s == 0) {
                float z = sZ[j][ci];
                float sil = z / (1.f + __expf(-z));
                y[(tokb + l0 + j) * DI_ + c] = (py + ut * Dc) * sil;
            }
        }
    }
}

// ---------------- launcher ----------------
extern "C" void kernel_launch(void* const* d_in, const int* in_sizes, int n_in,
                              void* d_out, int out_size)
{
    const float* x        = (const float*)d_in[0];
    const float* conv1w   = (const float*)d_in[1];
    const float* conv1b   = (const float*)d_in[2];
    const float* conv2w   = (const float*)d_in[3];
    const float* conv2b   = (const float*)d_in[4];
    const float* ln_g     = (const float*)d_in[5];
    const float* ln_b     = (const float*)d_in[6];
    const float* inprojw  = (const float*)d_in[7];
    const float* c1dw     = (const float*)d_in[8];
    const float* c1db     = (const float*)d_in[9];
    const float* xprojw   = (const float*)d_in[10];
    const float* dtprojw  = (const float*)d_in[11];
    const float* dtprojb  = (const float*)d_in[12];
    const float* A_log    = (const float*)d_in[13];
    const float* Dp       = (const float*)d_in[14];
    const float* outprojw = (const float*)d_in[15];
    float* out = (float*)d_out;

    float *buf1, *buf2, *xnorm, *xz, *u, *xdb, *delta, *y;
    float *wrp1, *wrp2, *psum, *psq, *mean, *rstd, *Aneg;
    void* p;
    cudaGetSymbolAddress(&p, g_buf1);  buf1  = (float*)p;
    cudaGetSymbolAddress(&p, g_buf2);  buf2  = (float*)p;
    cudaGetSymbolAddress(&p, g_xnorm); xnorm = (float*)p;
    cudaGetSymbolAddress(&p, g_xz);    xz    = (float*)p;
    cudaGetSymbolAddress(&p, g_u);     u     = (float*)p;
    cudaGetSymbolAddress(&p, g_xdb);   xdb   = (float*)p;
    cudaGetSymbolAddress(&p, g_delta); delta = (float*)p;
    cudaGetSymbolAddress(&p, g_y);     y     = (float*)p;
    cudaGetSymbolAddress(&p, g_wrp1);  wrp1  = (float*)p;
    cudaGetSymbolAddress(&p, g_wrp2);  wrp2  = (float*)p;
    cudaGetSymbolAddress(&p, g_psum);  psum  = (float*)p;
    cudaGetSymbolAddress(&p, g_psq);   psq   = (float*)p;
    cudaGetSymbolAddress(&p, g_mean);  mean  = (float*)p;
    cudaGetSymbolAddress(&p, g_rstd);  rstd  = (float*)p;
    cudaGetSymbolAddress(&p, g_Aneg);  Aneg  = (float*)p;

    const int M = B_ * L_;               // 32768 tokens
    dim3 cgrid(H_, T_, B_);

    // conv weight repack (both)
    repack_w<<<(27 * C_ * C_ + 255) / 256, 256>>>(conv1w, wrp1);
    repack_w<<<(27 * C_ * C_ + 255) / 256, 256>>>(conv2w, wrp2);

    // conv1 -> inorm -> leaky
    conv3d_k<<<cgrid, 256>>>(x, wrp1, conv1b, buf1);
    inorm_part<<<dim3(128, B_), 192>>>(buf1, psum, psq);
    inorm_fin<<<B_, 192>>>(psum, psq, mean, rstd);
    ew_leaky<<<(B_ * L_ * C_ + 255) / 256, 256>>>(buf1, mean, rstd);

    // conv2 -> inorm -> +residual(x)
    conv3d_k<<<cgrid, 256>>>(buf1, wrp2, conv2b, buf2);
    inorm_part<<<dim3(128, B_), 192>>>(buf2, psum, psq);
    inorm_fin<<<B_, 192>>>(psum, psq, mean, rstd);
    ew_res<<<(B_ * L_ * C_ + 255) / 256, 256>>>(buf2, mean, rstd, x);

    // reshaped LayerNorm
    weird_ln<<<(B_ * L_ + 255) / 256, 256>>>(buf2, ln_g, ln_b, xnorm);

    // xz = xnorm @ in_proj^T   (M x 768, K=192)
    sgemm_nt<<<dim3(768 / 64, M / 128), 256>>>(xnorm, inprojw, xz,
                                               M, 2 * DI_, C_, C_, C_, 2 * DI_, nullptr, 0);
    // depthwise conv1d + silu -> u
    conv1d_silu<<<(B_ * L_ * DI_ + 255) / 256, 256>>>(xz, c1dw, c1db, u);

    // xdb = u @ x_proj^T   (M x 44, K=384)
    sgemm_nt<<<dim3(1, M / 128), 256>>>(u, xprojw, xdb,
                                        M, XW_, DI_, DI_, DI_, XW_, nullptr, 0);
    // delta = softplus(dt @ dt_proj^T + b)   (M x 384, K=12, A stride 44)
    sgemm_nt<<<dim3(DI_ / 64, M / 128), 256>>>(xdb, dtprojw, delta,
                                               M, DI_, 12, XW_, 12, DI_, dtprojb, 1);

    // A = -exp(A_log)
    prep_A<<<(DI_ * DS_ + 255) / 256, 256>>>(A_log, Aneg);

    // selective scan (+u*Dp, *silu(z) fused)
    scan_k<<<dim3(DI_ / 8, B_), 128>>>(delta, u, xz, xdb, Aneg, Dp, y);

    // out = y @ out_proj^T   (M x 192, K=384) -> d_out
    sgemm_nt<<<dim3(C_ / 64, M / 128), 256>>>(y, outprojw, out,
                                              M, C_, DI_, DI_, DI_, C_, nullptr, 0);
}